// round 7
// baseline (speedup 1.0000x reference)
#include <cuda_runtime.h>

// DynamicPooling R7: full-wave grid (592 blocks = 148 SMs x 4).
// B=64, N=4096, D=256, fp32. x: [B,N,D], m: [B,N,1]. Out: w [B,N], s [B,D].
//
// vs R6: N chunked into 37 uneven chunks per batch (26x111 + 11x110) so each
// sweep launch is exactly one full wave (37*16 = 592 = 148 SMs * 4 blocks).
// Rows are warp-strided; rolling prefetch depth 3 kept; max-free exp weights.

namespace {
constexpr int Bb = 64;
constexpr int Nn = 4096;
constexpr int Dd = 256;
constexpr int NCHUNK = 37;            // chunks per batch (grid.x)
constexpr int CH_BASE = Nn / NCHUNK;  // 110
constexpr int CH_REM = Nn % NCHUNK;   // 26 chunks get +1 row
constexpr int MAXROWS = CH_BASE + 1;  // 111
constexpr int WARPS = 8;
constexpr int GRP = 16;               // batches per group
constexpr int PF = 3;                 // prefetch depth (warp-strided rows)
}

__device__ float g_part[Bb * NCHUNK * Dd];  // unnormalized sigma partials [b][c][d]
__device__ float g_Z[Bb * NCHUNK];          // per-chunk mass [b][c]
__device__ float g_b[Bb * Nn];

// MODE 0: sigma only (uniform weights). MODE 1: head-combine -> s; b-update;
// next-sigma partials. MODE 2: head-combine -> s (write out_s); b-update only.
// ZEROB: incoming b treated as 0.
template <int MODE, bool ZEROB>
__global__ void __launch_bounds__(256, 4) fused_sweep_kernel(
    const float* x, const float* __restrict__ m,
    int b0, float* __restrict__ out_s) {
    const int b = b0 + blockIdx.y;
    const int c = blockIdx.x;
    const int t = threadIdx.x, w = t >> 5, l = t & 31;
    const int n0 = c * CH_BASE + min(c, CH_REM);
    const int rows = CH_BASE + (c < CH_REM ? 1 : 0);

    __shared__ float s_sh[Dd];
    __shared__ float m_sh[MAXROWS + 1];
    __shared__ float b_sh[MAXROWS + 1];
    __shared__ float sm_acc[WARPS * Dd];
    __shared__ float sm_Z[WARPS];
    __shared__ float red[256];
    __shared__ float hz[NCHUNK];

    if (t < rows) {
        int gi = b * Nn + n0 + t;
        m_sh[t] = m[gi];
        if (MODE != 0) b_sh[t] = ZEROB ? 0.0f : g_b[gi];
    }

    if (MODE != 0) {
        // head-combine: rebuild s from previous sweep's partials
        // (weights were raw exp(m*b): sum partials / sum masses).
        if (t < NCHUNK) hz[t] = g_Z[b * NCHUNK + t];
        __syncthreads();
        float v = 0.0f, Zg = 0.0f;
#pragma unroll
        for (int k = 0; k < NCHUNK; k++) {
            v += g_part[((size_t)b * NCHUNK + k) * Dd + t];
            Zg += hz[k];
        }
        const float sigma = v / Zg;
        red[t] = sigma * sigma;
        __syncthreads();
#pragma unroll
        for (int s = 128; s > 0; s >>= 1) {
            if (t < s) red[t] += red[t + s];
            __syncthreads();
        }
        const float n2 = red[0];
        const float norm = sqrtf(n2);
        const float sv = (n2 / (1.0f + n2) / (norm + 1e-8f)) * sigma;
        s_sh[t] = sv;
        if (MODE == 2 && c == 0 && out_s) out_s[b * Dd + t] = sv;
    }
    __syncthreads();

    const float* xb = x + ((size_t)b * Nn + n0) * Dd;
    const int d0 = l << 2;

    // warp-strided rows: warp w handles i = w, w+8, w+16, ...
    // rolling prefetch depth PF (indices w + j*WARPS, always < rows for j<PF)
    float4 pa[PF], pb[PF];
#pragma unroll
    for (int j = 0; j < PF; j++) {
        const float* xr = xb + (size_t)(w + j * WARPS) * Dd;
        pa[j] = *reinterpret_cast<const float4*>(xr + d0);
        pb[j] = *reinterpret_cast<const float4*>(xr + 128 + d0);
    }

    float acc[8] = {0, 0, 0, 0, 0, 0, 0, 0};
    float Z = 0.0f;
    int slot = 0;

    for (int i = w; i < rows; i += WARPS) {
        const float4 a0 = pa[slot];
        const float4 a1 = pb[slot];
        const int nf = i + PF * WARPS;
        if (nf < rows) {
            const float* xn = xb + (size_t)nf * Dd;
            pa[slot] = *reinterpret_cast<const float4*>(xn + d0);
            pb[slot] = *reinterpret_cast<const float4*>(xn + 128 + d0);
        }
        if (++slot == PF) slot = 0;
        const float mn = m_sh[i];

        if (MODE == 0) {
            acc[0] = fmaf(mn, a0.x, acc[0]);
            acc[1] = fmaf(mn, a0.y, acc[1]);
            acc[2] = fmaf(mn, a0.z, acc[2]);
            acc[3] = fmaf(mn, a0.w, acc[3]);
            acc[4] = fmaf(mn, a1.x, acc[4]);
            acc[5] = fmaf(mn, a1.y, acc[5]);
            acc[6] = fmaf(mn, a1.z, acc[6]);
            acc[7] = fmaf(mn, a1.w, acc[7]);
            Z += 1.0f;
        } else {
            float dot = a0.x * s_sh[d0]       + a0.y * s_sh[d0 + 1] +
                        a0.z * s_sh[d0 + 2]   + a0.w * s_sh[d0 + 3] +
                        a1.x * s_sh[128 + d0] + a1.y * s_sh[129 + d0] +
                        a1.z * s_sh[130 + d0] + a1.w * s_sh[131 + d0];
#pragma unroll
            for (int o = 16; o > 0; o >>= 1)
                dot += __shfl_xor_sync(0xffffffffu, dot, o);

            const float bnew = fmaf(mn, dot, b_sh[i]);
            if (l == 0) g_b[b * Nn + n0 + i] = bnew;

            if (MODE == 1) {
                // raw exp weight, no max subtraction (|m*bnew| <= ~24, safe)
                const float e = __expf(mn * bnew);
                Z += e;
                const float wv = e * mn;
                acc[0] = fmaf(wv, a0.x, acc[0]);
                acc[1] = fmaf(wv, a0.y, acc[1]);
                acc[2] = fmaf(wv, a0.z, acc[2]);
                acc[3] = fmaf(wv, a0.w, acc[3]);
                acc[4] = fmaf(wv, a1.x, acc[4]);
                acc[5] = fmaf(wv, a1.y, acc[5]);
                acc[6] = fmaf(wv, a1.z, acc[6]);
                acc[7] = fmaf(wv, a1.w, acc[7]);
            }
        }
    }

    if (MODE != 2) {
        *reinterpret_cast<float4*>(&sm_acc[w * Dd + d0]) =
            make_float4(acc[0], acc[1], acc[2], acc[3]);
        *reinterpret_cast<float4*>(&sm_acc[w * Dd + 128 + d0]) =
            make_float4(acc[4], acc[5], acc[6], acc[7]);
        if (l == 0) sm_Z[w] = Z;
        __syncthreads();

        float sig = 0.0f;
#pragma unroll
        for (int k = 0; k < WARPS; k++)
            sig += sm_acc[k * Dd + t];
        g_part[((size_t)b * NCHUNK + c) * Dd + t] = sig;
        if (t == 0) {
            float Zb = 0.0f;
#pragma unroll
            for (int k = 0; k < WARPS; k++) Zb += sm_Z[k];
            g_Z[b * NCHUNK + c] = Zb;
        }
    }
}

// Final w = softmax(b) over N (no m factor). Exact 2-pass in-register.
__global__ void __launch_bounds__(256) final_softmax_kernel(float* __restrict__ out_w) {
    const int b = blockIdx.x, t = threadIdx.x;
    const float* bb = g_b + (size_t)b * Nn;

    float vals[16];
    float lmax = -3.4e38f;
#pragma unroll
    for (int i = 0; i < 16; i++) {
        vals[i] = bb[t + i * 256];
        lmax = fmaxf(lmax, vals[i]);
    }
    __shared__ float red[256];
    red[t] = lmax;
    __syncthreads();
#pragma unroll
    for (int s = 128; s > 0; s >>= 1) {
        if (t < s) red[t] = fmaxf(red[t], red[t + s]);
        __syncthreads();
    }
    const float gmax = red[0];
    __syncthreads();

    float lsum = 0.0f;
#pragma unroll
    for (int i = 0; i < 16; i++) {
        vals[i] = __expf(vals[i] - gmax);
        lsum += vals[i];
    }
    red[t] = lsum;
    __syncthreads();
#pragma unroll
    for (int s = 128; s > 0; s >>= 1) {
        if (t < s) red[t] += red[t + s];
        __syncthreads();
    }
    const float inv = 1.0f / red[0];
#pragma unroll
    for (int i = 0; i < 16; i++)
        out_w[(size_t)b * Nn + t + i * 256] = vals[i] * inv;
}

extern "C" void kernel_launch(void* const* d_in, const int* in_sizes, int n_in,
                              void* d_out, int out_size) {
    (void)in_sizes; (void)n_in; (void)out_size;
    const float* x = (const float*)d_in[0];
    const float* m = (const float*)d_in[1];
    float* out = (float*)d_out;
    float* out_w = out;             // [B, N]
    float* out_s = out + Bb * Nn;   // [B, D]

    const dim3 grid(NCHUNK, GRP);   // 37 x 16 = 592 blocks = 148 SMs x 4

    for (int g = 0; g < Bb / GRP; ++g) {
        const int b0 = g * GRP;
        fused_sweep_kernel<0, false><<<grid, 256>>>(x, m, b0, nullptr); // sigma1
        fused_sweep_kernel<1, true><<<grid, 256>>>(x, m, b0, nullptr);  // b1+sigma2
        fused_sweep_kernel<1, false><<<grid, 256>>>(x, m, b0, nullptr); // b2+sigma3
        fused_sweep_kernel<2, false><<<grid, 256>>>(x, m, b0, out_s);   // s3+b3
    }
    final_softmax_kernel<<<Bb, 256>>>(out_w);  // w = softmax(b3)
}

// round 9
// speedup vs baseline: 1.6218x; 1.6218x over previous
#include <cuda_runtime.h>
#include <cuda_fp16.h>
#include <cstdint>

// DynamicPooling R9 (= R8 + include fix): fp16 y-cache (y = m*x computed
// once), L2-resident groups. B=64, N=4096, D=256.
// x: [B,N,D] f32, m: [B,N,1] f32. Out: w [B,N], s [B,D].
//
// Per group of 16 batches (4 sweeps of the group's slice):
//   sweep 0 (MODE 0): read x f32 (64MB), y = m*x -> fp16 cache (32MB write),
//                     accumulate sigma1 partials (uniform weights).
//   sweep 1 (MODE 1, ZEROB): head-combine -> s1; b1 = dot(s1,y); sigma2 (exp
//                     weights, no max: |m*b| <= ~24 safe in f32).
//   sweep 2 (MODE 1): -> s2; b2 += dot; sigma3.
//   sweep 3 (MODE 2): -> s3 (write out); b3 += dot.
// Sweeps 1-3 read fp16 y (32MB -> L2-resident). Final: w = softmax(b3).
// All loops compile-time trip count (R7 lesson: no dynamic reg-array idx).

namespace {
constexpr int Bb = 64;
constexpr int Nn = 4096;
constexpr int Dd = 256;
constexpr int NCHUNK = 32;            // N-chunks per batch
constexpr int ROWS = Nn / NCHUNK;     // 128 rows per block
constexpr int WARPS = 8;
constexpr int RPW = ROWS / WARPS;     // 16 rows per warp (compile-time)
constexpr int GRP = 16;               // batches per group
constexpr int PF = 3;                 // prefetch depth (rows)
}

__device__ __half g_y[(size_t)Bb * Nn * Dd];  // fp16 cache of m*x (128MB)
__device__ float g_part[Bb * NCHUNK * Dd];    // unnormalized sigma partials
__device__ float g_Z[Bb * NCHUNK];            // per-chunk mass
__device__ float g_b[Bb * Nn];

__device__ __forceinline__ unsigned int pack2(float a, float b) {
    __half2 h = __floats2half2_rn(a, b);
    return *reinterpret_cast<unsigned int*>(&h);
}
__device__ __forceinline__ float2 unpack2(unsigned int u) {
    return __half22float2(*reinterpret_cast<__half2*>(&u));
}

// MODE 0: convert+sigma. MODE 1: head-combine -> s; b-update; next sigma.
// MODE 2: head-combine -> s (write out_s); b-update only.
template <int MODE, bool ZEROB>
__global__ void __launch_bounds__(256, 4) fused_sweep_kernel(
    const float* x, const float* __restrict__ m,
    int b0, float* __restrict__ out_s) {
    const int b = b0 + blockIdx.y;
    const int c = blockIdx.x;
    const int t = threadIdx.x, w = t >> 5, l = t & 31;
    const int n0 = c * ROWS;

    __shared__ float s_sh[Dd];
    __shared__ float m_sh[ROWS];
    __shared__ float b_sh[ROWS];
    __shared__ float sm_acc[WARPS * Dd];
    __shared__ float sm_Z[WARPS];
    __shared__ float red[256];
    __shared__ float hz[NCHUNK];

    if (t < ROWS) {
        int gi = b * Nn + n0 + t;
        m_sh[t] = m[gi];
        if (MODE != 0) b_sh[t] = ZEROB ? 0.0f : g_b[gi];
    }

    if (MODE != 0) {
        // head-combine: s from previous sweep's partials (sum/mass, no exps)
        if (t < NCHUNK) hz[t] = g_Z[b * NCHUNK + t];
        __syncthreads();
        float v = 0.0f, Zg = 0.0f;
#pragma unroll
        for (int k = 0; k < NCHUNK; k++) {
            v += g_part[((size_t)b * NCHUNK + k) * Dd + t];
            Zg += hz[k];
        }
        const float sigma = v / Zg;
        red[t] = sigma * sigma;
        __syncthreads();
#pragma unroll
        for (int s = 128; s > 0; s >>= 1) {
            if (t < s) red[t] += red[t + s];
            __syncthreads();
        }
        const float n2 = red[0];
        const float norm = sqrtf(n2);
        const float sv = (n2 / (1.0f + n2) / (norm + 1e-8f)) * sigma;
        s_sh[t] = sv;
        if (MODE == 2 && c == 0 && out_s) out_s[b * Dd + t] = sv;
    }
    __syncthreads();

    const size_t rowbase = (size_t)b * Nn + n0;
    const int d0 = l << 2;        // f32 path: lane's 2 float4 offsets (d0, d0+128)
    const int h0 = l << 3;        // f16 path: lane owns 8 halfs at h0

    float acc[8] = {0, 0, 0, 0, 0, 0, 0, 0};
    float Z = 0.0f;

    if (MODE == 0) {
        const float* xb = x + rowbase * Dd;
        float4 pa[PF], pb[PF];
#pragma unroll
        for (int j = 0; j < PF; j++) {
            const float* xr = xb + (size_t)(w * RPW + j) * Dd;
            pa[j] = *reinterpret_cast<const float4*>(xr + d0);
            pb[j] = *reinterpret_cast<const float4*>(xr + 128 + d0);
        }
#pragma unroll
        for (int i = 0; i < RPW; i++) {
            const int n = w * RPW + i;
            const float4 a0 = pa[i % PF];
            const float4 a1 = pb[i % PF];
            if (i + PF < RPW) {
                const float* xn = xb + (size_t)(n + PF) * Dd;
                pa[i % PF] = *reinterpret_cast<const float4*>(xn + d0);
                pb[i % PF] = *reinterpret_cast<const float4*>(xn + 128 + d0);
            }
            const float mn = m_sh[n];
            // y = m*x (8 values: cols d0..d0+3 and 128+d0..128+d0+3)
            const float y0 = mn * a0.x, y1 = mn * a0.y, y2 = mn * a0.z, y3 = mn * a0.w;
            const float y4 = mn * a1.x, y5 = mn * a1.y, y6 = mn * a1.z, y7 = mn * a1.w;
            acc[0] += y0; acc[1] += y1; acc[2] += y2; acc[3] += y3;
            acc[4] += y4; acc[5] += y5; acc[6] += y6; acc[7] += y7;
            Z += 1.0f;
            // store fp16: lane writes its two 8-byte groups
            uint2 ua = make_uint2(pack2(y0, y1), pack2(y2, y3));
            uint2 ub = make_uint2(pack2(y4, y5), pack2(y6, y7));
            __half* yr = g_y + ((size_t)(rowbase + n)) * Dd;
            *reinterpret_cast<uint2*>(yr + d0) = ua;
            *reinterpret_cast<uint2*>(yr + 128 + d0) = ub;
        }
    } else {
        const __half* yb = g_y + rowbase * Dd;
        uint4 py[PF];
#pragma unroll
        for (int j = 0; j < PF; j++)
            py[j] = *reinterpret_cast<const uint4*>(yb + (size_t)(w * RPW + j) * Dd + h0);

#pragma unroll
        for (int i = 0; i < RPW; i++) {
            const int n = w * RPW + i;
            const uint4 u = py[i % PF];
            if (i + PF < RPW)
                py[i % PF] = *reinterpret_cast<const uint4*>(
                    yb + (size_t)(n + PF) * Dd + h0);

            const float2 f0 = unpack2(u.x), f1 = unpack2(u.y),
                         f2 = unpack2(u.z), f3 = unpack2(u.w);
            const float mn = m_sh[n];

            // dot(s, y_n): lane owns cols h0..h0+7
            float dot = f0.x * s_sh[h0]     + f0.y * s_sh[h0 + 1] +
                        f1.x * s_sh[h0 + 2] + f1.y * s_sh[h0 + 3] +
                        f2.x * s_sh[h0 + 4] + f2.y * s_sh[h0 + 5] +
                        f3.x * s_sh[h0 + 6] + f3.y * s_sh[h0 + 7];
#pragma unroll
            for (int o = 16; o > 0; o >>= 1)
                dot += __shfl_xor_sync(0xffffffffu, dot, o);

            const float bnew = b_sh[n] + dot;   // y already includes m
            if (l == 0) g_b[b * Nn + n0 + n] = bnew;

            if (MODE == 1) {
                const float e = __expf(mn * bnew);  // raw weight, no max: safe
                Z += e;
                acc[0] = fmaf(e, f0.x, acc[0]);
                acc[1] = fmaf(e, f0.y, acc[1]);
                acc[2] = fmaf(e, f1.x, acc[2]);
                acc[3] = fmaf(e, f1.y, acc[3]);
                acc[4] = fmaf(e, f2.x, acc[4]);
                acc[5] = fmaf(e, f2.y, acc[5]);
                acc[6] = fmaf(e, f3.x, acc[6]);
                acc[7] = fmaf(e, f3.y, acc[7]);
            }
        }
    }

    if (MODE != 2) {
        // per-warp partials -> block combine (fixed order). Note: MODE 0
        // lane layout is (d0, 128+d0); MODE 1 layout is h0..h0+7.
        if (MODE == 0) {
            *reinterpret_cast<float4*>(&sm_acc[w * Dd + d0]) =
                make_float4(acc[0], acc[1], acc[2], acc[3]);
            *reinterpret_cast<float4*>(&sm_acc[w * Dd + 128 + d0]) =
                make_float4(acc[4], acc[5], acc[6], acc[7]);
        } else {
            *reinterpret_cast<float4*>(&sm_acc[w * Dd + h0]) =
                make_float4(acc[0], acc[1], acc[2], acc[3]);
            *reinterpret_cast<float4*>(&sm_acc[w * Dd + h0 + 4]) =
                make_float4(acc[4], acc[5], acc[6], acc[7]);
        }
        if (l == 0) sm_Z[w] = Z;
        __syncthreads();

        float sig = 0.0f;
#pragma unroll
        for (int k = 0; k < WARPS; k++)
            sig += sm_acc[k * Dd + t];
        g_part[((size_t)b * NCHUNK + c) * Dd + t] = sig;
        if (t == 0) {
            float Zb = 0.0f;
#pragma unroll
            for (int k = 0; k < WARPS; k++) Zb += sm_Z[k];
            g_Z[b * NCHUNK + c] = Zb;
        }
    }
}

// Final w = softmax(b) over N (no m factor). Exact 2-pass in-register.
__global__ void __launch_bounds__(256) final_softmax_kernel(float* __restrict__ out_w) {
    const int b = blockIdx.x, t = threadIdx.x;
    const float* bb = g_b + (size_t)b * Nn;

    float vals[16];
    float lmax = -3.4e38f;
#pragma unroll
    for (int i = 0; i < 16; i++) {
        vals[i] = bb[t + i * 256];
        lmax = fmaxf(lmax, vals[i]);
    }
    __shared__ float red[256];
    red[t] = lmax;
    __syncthreads();
#pragma unroll
    for (int s = 128; s > 0; s >>= 1) {
        if (t < s) red[t] = fmaxf(red[t], red[t + s]);
        __syncthreads();
    }
    const float gmax = red[0];
    __syncthreads();

    float lsum = 0.0f;
#pragma unroll
    for (int i = 0; i < 16; i++) {
        vals[i] = __expf(vals[i] - gmax);
        lsum += vals[i];
    }
    red[t] = lsum;
    __syncthreads();
#pragma unroll
    for (int s = 128; s > 0; s >>= 1) {
        if (t < s) red[t] += red[t + s];
        __syncthreads();
    }
    const float inv = 1.0f / red[0];
#pragma unroll
    for (int i = 0; i < 16; i++)
        out_w[(size_t)b * Nn + t + i * 256] = vals[i] * inv;
}

extern "C" void kernel_launch(void* const* d_in, const int* in_sizes, int n_in,
                              void* d_out, int out_size) {
    (void)in_sizes; (void)n_in; (void)out_size;
    const float* x = (const float*)d_in[0];
    const float* m = (const float*)d_in[1];
    float* out = (float*)d_out;
    float* out_w = out;             // [B, N]
    float* out_s = out + Bb * Nn;   // [B, D]

    const dim3 grid(NCHUNK, GRP);

    for (int g = 0; g < Bb / GRP; ++g) {
        const int b0 = g * GRP;
        fused_sweep_kernel<0, false><<<grid, 256>>>(x, m, b0, nullptr); // y + sigma1
        fused_sweep_kernel<1, true><<<grid, 256>>>(x, m, b0, nullptr);  // b1 + sigma2
        fused_sweep_kernel<1, false><<<grid, 256>>>(x, m, b0, nullptr); // b2 + sigma3
        fused_sweep_kernel<2, false><<<grid, 256>>>(x, m, b0, out_s);   // s3 + b3
    }
    final_softmax_kernel<<<Bb, 256>>>(out_w);  // w = softmax(b3)
}

// round 11
// speedup vs baseline: 1.6801x; 1.0360x over previous
#include <cuda_runtime.h>
#include <cuda_fp16.h>
#include <cstdint>

// DynamicPooling R11: R9 kernels + two-stream overlap with PROPER graph fork.
// B=64, N=4096, D=256. x f32 [B,N,D], m f32 [B,N,1]. Out: w [B,N], s [B,D].
//
// Capture-legal fork-join: record root event on the capture-origin stream,
// side stream waits on it (joining the capture), fills run there, per-group
// events gate the main stream's reuse sweeps. Fill(g+1) (DRAM-bound) overlaps
// group g's reuse sweeps (L2/issue-bound). Buffers batch-partitioned: no alias.

namespace {
constexpr int Bb = 64;
constexpr int Nn = 4096;
constexpr int Dd = 256;
constexpr int NCHUNK = 32;            // N-chunks per batch
constexpr int ROWS = Nn / NCHUNK;     // 128 rows per block
constexpr int WARPS = 8;
constexpr int RPW = ROWS / WARPS;     // 16 rows per warp (compile-time)
constexpr int GRP = 16;               // batches per group
constexpr int NGRP = Bb / GRP;        // 4 groups
constexpr int PF = 3;                 // prefetch depth (rows)
}

__device__ __half g_y[(size_t)Bb * Nn * Dd];  // fp16 cache of m*x (128MB)
__device__ float g_part[Bb * NCHUNK * Dd];    // unnormalized sigma partials
__device__ float g_Z[Bb * NCHUNK];            // per-chunk mass
__device__ float g_b[Bb * Nn];

// Host-side stream/event kit (host resources only; no device memory).
namespace {
struct StreamKit {
    cudaStream_t s1;
    cudaEvent_t ev_root;
    cudaEvent_t ev_fill[NGRP];
    StreamKit() {
        cudaStreamCreateWithFlags(&s1, cudaStreamNonBlocking);
        cudaEventCreateWithFlags(&ev_root, cudaEventDisableTiming);
        for (int i = 0; i < NGRP; i++)
            cudaEventCreateWithFlags(&ev_fill[i], cudaEventDisableTiming);
    }
};
StreamKit g_kit;
}

__device__ __forceinline__ unsigned int pack2(float a, float b) {
    __half2 h = __floats2half2_rn(a, b);
    return *reinterpret_cast<unsigned int*>(&h);
}
__device__ __forceinline__ float2 unpack2(unsigned int u) {
    return __half22float2(*reinterpret_cast<__half2*>(&u));
}

// MODE 0: convert+sigma. MODE 1: head-combine -> s; b-update; next sigma.
// MODE 2: head-combine -> s (write out_s); b-update only.
template <int MODE, bool ZEROB>
__global__ void __launch_bounds__(256, 4) fused_sweep_kernel(
    const float* x, const float* __restrict__ m,
    int b0, float* __restrict__ out_s) {
    const int b = b0 + blockIdx.y;
    const int c = blockIdx.x;
    const int t = threadIdx.x, w = t >> 5, l = t & 31;
    const int n0 = c * ROWS;

    __shared__ float s_sh[Dd];
    __shared__ float m_sh[ROWS];
    __shared__ float b_sh[ROWS];
    __shared__ float sm_acc[WARPS * Dd];
    __shared__ float sm_Z[WARPS];
    __shared__ float red[256];
    __shared__ float hz[NCHUNK];

    if (t < ROWS) {
        int gi = b * Nn + n0 + t;
        m_sh[t] = m[gi];
        if (MODE != 0) b_sh[t] = ZEROB ? 0.0f : g_b[gi];
    }

    if (MODE != 0) {
        // head-combine: s from previous sweep's partials (sum/mass, no exps)
        if (t < NCHUNK) hz[t] = g_Z[b * NCHUNK + t];
        __syncthreads();
        float v = 0.0f, Zg = 0.0f;
#pragma unroll
        for (int k = 0; k < NCHUNK; k++) {
            v += g_part[((size_t)b * NCHUNK + k) * Dd + t];
            Zg += hz[k];
        }
        const float sigma = v / Zg;
        red[t] = sigma * sigma;
        __syncthreads();
#pragma unroll
        for (int s = 128; s > 0; s >>= 1) {
            if (t < s) red[t] += red[t + s];
            __syncthreads();
        }
        const float n2 = red[0];
        const float norm = sqrtf(n2);
        const float sv = (n2 / (1.0f + n2) / (norm + 1e-8f)) * sigma;
        s_sh[t] = sv;
        if (MODE == 2 && c == 0 && out_s) out_s[b * Dd + t] = sv;
    }
    __syncthreads();

    const size_t rowbase = (size_t)b * Nn + n0;
    const int d0 = l << 2;        // f32 path lane offsets (d0, d0+128)
    const int h0 = l << 3;        // f16 path: lane owns 8 halfs at h0

    float acc[8] = {0, 0, 0, 0, 0, 0, 0, 0};
    float Z = 0.0f;

    if (MODE == 0) {
        const float* xb = x + rowbase * Dd;
        float4 pa[PF], pb[PF];
#pragma unroll
        for (int j = 0; j < PF; j++) {
            const float* xr = xb + (size_t)(w * RPW + j) * Dd;
            pa[j] = *reinterpret_cast<const float4*>(xr + d0);
            pb[j] = *reinterpret_cast<const float4*>(xr + 128 + d0);
        }
#pragma unroll
        for (int i = 0; i < RPW; i++) {
            const int n = w * RPW + i;
            const float4 a0 = pa[i % PF];
            const float4 a1 = pb[i % PF];
            if (i + PF < RPW) {
                const float* xn = xb + (size_t)(n + PF) * Dd;
                pa[i % PF] = *reinterpret_cast<const float4*>(xn + d0);
                pb[i % PF] = *reinterpret_cast<const float4*>(xn + 128 + d0);
            }
            const float mn = m_sh[n];
            const float y0 = mn * a0.x, y1 = mn * a0.y, y2 = mn * a0.z, y3 = mn * a0.w;
            const float y4 = mn * a1.x, y5 = mn * a1.y, y6 = mn * a1.z, y7 = mn * a1.w;
            acc[0] += y0; acc[1] += y1; acc[2] += y2; acc[3] += y3;
            acc[4] += y4; acc[5] += y5; acc[6] += y6; acc[7] += y7;
            Z += 1.0f;
            uint2 ua = make_uint2(pack2(y0, y1), pack2(y2, y3));
            uint2 ub = make_uint2(pack2(y4, y5), pack2(y6, y7));
            __half* yr = g_y + ((size_t)(rowbase + n)) * Dd;
            *reinterpret_cast<uint2*>(yr + d0) = ua;
            *reinterpret_cast<uint2*>(yr + 128 + d0) = ub;
        }
    } else {
        const __half* yb = g_y + rowbase * Dd;
        uint4 py[PF];
#pragma unroll
        for (int j = 0; j < PF; j++)
            py[j] = *reinterpret_cast<const uint4*>(yb + (size_t)(w * RPW + j) * Dd + h0);

#pragma unroll
        for (int i = 0; i < RPW; i++) {
            const int n = w * RPW + i;
            const uint4 u = py[i % PF];
            if (i + PF < RPW)
                py[i % PF] = *reinterpret_cast<const uint4*>(
                    yb + (size_t)(n + PF) * Dd + h0);

            const float2 f0 = unpack2(u.x), f1 = unpack2(u.y),
                         f2 = unpack2(u.z), f3 = unpack2(u.w);
            const float mn = m_sh[n];

            float dot = f0.x * s_sh[h0]     + f0.y * s_sh[h0 + 1] +
                        f1.x * s_sh[h0 + 2] + f1.y * s_sh[h0 + 3] +
                        f2.x * s_sh[h0 + 4] + f2.y * s_sh[h0 + 5] +
                        f3.x * s_sh[h0 + 6] + f3.y * s_sh[h0 + 7];
#pragma unroll
            for (int o = 16; o > 0; o >>= 1)
                dot += __shfl_xor_sync(0xffffffffu, dot, o);

            const float bnew = b_sh[n] + dot;   // y already includes m
            if (l == 0) g_b[b * Nn + n0 + n] = bnew;

            if (MODE == 1) {
                const float e = __expf(mn * bnew);  // raw weight, no max: safe
                Z += e;
                acc[0] = fmaf(e, f0.x, acc[0]);
                acc[1] = fmaf(e, f0.y, acc[1]);
                acc[2] = fmaf(e, f1.x, acc[2]);
                acc[3] = fmaf(e, f1.y, acc[3]);
                acc[4] = fmaf(e, f2.x, acc[4]);
                acc[5] = fmaf(e, f2.y, acc[5]);
                acc[6] = fmaf(e, f3.x, acc[6]);
                acc[7] = fmaf(e, f3.y, acc[7]);
            }
        }
    }

    if (MODE != 2) {
        if (MODE == 0) {
            *reinterpret_cast<float4*>(&sm_acc[w * Dd + d0]) =
                make_float4(acc[0], acc[1], acc[2], acc[3]);
            *reinterpret_cast<float4*>(&sm_acc[w * Dd + 128 + d0]) =
                make_float4(acc[4], acc[5], acc[6], acc[7]);
        } else {
            *reinterpret_cast<float4*>(&sm_acc[w * Dd + h0]) =
                make_float4(acc[0], acc[1], acc[2], acc[3]);
            *reinterpret_cast<float4*>(&sm_acc[w * Dd + h0 + 4]) =
                make_float4(acc[4], acc[5], acc[6], acc[7]);
        }
        if (l == 0) sm_Z[w] = Z;
        __syncthreads();

        float sig = 0.0f;
#pragma unroll
        for (int k = 0; k < WARPS; k++)
            sig += sm_acc[k * Dd + t];
        g_part[((size_t)b * NCHUNK + c) * Dd + t] = sig;
        if (t == 0) {
            float Zb = 0.0f;
#pragma unroll
            for (int k = 0; k < WARPS; k++) Zb += sm_Z[k];
            g_Z[b * NCHUNK + c] = Zb;
        }
    }
}

// Final w = softmax(b) over N (no m factor). Exact 2-pass in-register.
__global__ void __launch_bounds__(256) final_softmax_kernel(float* __restrict__ out_w) {
    const int b = blockIdx.x, t = threadIdx.x;
    const float* bb = g_b + (size_t)b * Nn;

    float vals[16];
    float lmax = -3.4e38f;
#pragma unroll
    for (int i = 0; i < 16; i++) {
        vals[i] = bb[t + i * 256];
        lmax = fmaxf(lmax, vals[i]);
    }
    __shared__ float red[256];
    red[t] = lmax;
    __syncthreads();
#pragma unroll
    for (int s = 128; s > 0; s >>= 1) {
        if (t < s) red[t] = fmaxf(red[t], red[t + s]);
        __syncthreads();
    }
    const float gmax = red[0];
    __syncthreads();

    float lsum = 0.0f;
#pragma unroll
    for (int i = 0; i < 16; i++) {
        vals[i] = __expf(vals[i] - gmax);
        lsum += vals[i];
    }
    red[t] = lsum;
    __syncthreads();
#pragma unroll
    for (int s = 128; s > 0; s >>= 1) {
        if (t < s) red[t] += red[t + s];
        __syncthreads();
    }
    const float inv = 1.0f / red[0];
#pragma unroll
    for (int i = 0; i < 16; i++)
        out_w[(size_t)b * Nn + t + i * 256] = vals[i] * inv;
}

extern "C" void kernel_launch(void* const* d_in, const int* in_sizes, int n_in,
                              void* d_out, int out_size) {
    (void)in_sizes; (void)n_in; (void)out_size;
    const float* x = (const float*)d_in[0];
    const float* m = (const float*)d_in[1];
    float* out = (float*)d_out;
    float* out_w = out;             // [B, N]
    float* out_s = out + Bb * Nn;   // [B, D]

    const dim3 grid(NCHUNK, GRP);

    // FORK: side stream joins the capture via a root event recorded on the
    // capture-origin stream (required for multi-stream graph capture).
    cudaEventRecord(g_kit.ev_root, 0);
    cudaStreamWaitEvent(g_kit.s1, g_kit.ev_root, 0);

    // Side stream: all 4 fill sweeps back-to-back (DRAM-bound).
    for (int g = 0; g < NGRP; ++g) {
        fused_sweep_kernel<0, false><<<grid, 256, 0, g_kit.s1>>>(
            x, m, g * GRP, nullptr);                       // y + sigma1
        cudaEventRecord(g_kit.ev_fill[g], g_kit.s1);
    }

    // Main stream: per-group reuse sweeps, gated on fill(g). The wait on
    // ev_fill[NGRP-1] also JOINS the side branch before the final node.
    for (int g = 0; g < NGRP; ++g) {
        const int b0 = g * GRP;
        cudaStreamWaitEvent(0, g_kit.ev_fill[g], 0);
        fused_sweep_kernel<1, true><<<grid, 256>>>(x, m, b0, nullptr);  // b1+sigma2
        fused_sweep_kernel<1, false><<<grid, 256>>>(x, m, b0, nullptr); // b2+sigma3
        fused_sweep_kernel<2, false><<<grid, 256>>>(x, m, b0, out_s);   // s3+b3
    }
    final_softmax_kernel<<<Bb, 256>>>(out_w);  // w = softmax(b3)
}